// round 14
// baseline (speedup 1.0000x reference)
#include <cuda_runtime.h>
#include <cstdint>

// ---------------------------------------------------------------------------
// SphericalExpansion, round 14: STRUCTURAL — eliminate the atomic-RMW wall.
//
// Evidence: R4..R13 all plateau at 82-87us with L2=52% across wildly
// different instruction mixes -> bound by 102.4M f32 atomic RMW at L2.
//
// New shape:
//   K0: head[s] = -1
//   K1: per edge, seg = 4*idx_i + z[idx_j]; next[e] = atomicExch(head[seg], e)
//       (4B atomic per edge instead of 512B RMW: 128x less atomic traffic)
//   K2: one warp per segment; walk the chain; lane L owns segment floats
//       {L, L+32, L+64, L+96} (lm = L&15, n = (L>>4)+2k) and accumulates in
//       REGISTERS; per edge: 1 exp (own rb, fc folded) + compact-Y +
//       4 shfl + 4 FMA; epilogue: 4 coalesced 128B stores (covers empty
//       segments too -> no zero-fill kernel).
// ---------------------------------------------------------------------------

#define NSEG_MAX 80000     // N_ATOMS * N_SPECIES
#define J_MAX    800000    // N_EDGES

__device__ int g_head[NSEG_MAX];
__device__ int g_next[J_MAX];

typedef unsigned long long u64;

// f1 selector: 0 = 1, 1 = x, 2 = y, 3 = z
__constant__ int cFS[16] = {0,2,3,1, 0,0,0,0, 0,2,1,2, 3,1,3,1};
// P,Q selectors for U1 = P*Q: 0 = x, 1 = y, 2 = z
__constant__ int cPQ[16][2] = {
    {0,0},{0,0},{0,0},{0,0},
    {0,1},{1,2},{0,0},{2,0},
    {0,0},{0,0},{1,2},{0,0},
    {0,0},{0,0},{0,0},{0,0},
};
// {C0, C1, C2}: Y = f1 * (C0 + C1*(P*Q) + C2*z2)  (y^2 removed via unit norm;
// verified R10-R13, rel_err ~1.5e-7)
__constant__ float cC[16][3] = {
    { 0.28209479177387814f, 0.f,                 0.f},
    { 0.4886025119029199f,  0.f,                 0.f},
    { 0.4886025119029199f,  0.f,                 0.f},
    { 0.4886025119029199f,  0.f,                 0.f},
    { 0.f,                  1.0925484305920792f, 0.f},
    { 0.f,                  1.0925484305920792f, 0.f},
    {-0.31539156525252005f, 0.f,                 0.9461746957575602f},
    { 0.f,                  1.0925484305920792f, 0.f},
    {-0.5462742152960396f,  1.0925484305920792f, 0.5462742152960396f},
    {-0.5900435899266435f,  2.360174359706574f,  0.5900435899266435f},
    { 0.f,                  2.890611442640554f,  0.f},
    {-0.4570457994644658f,  0.f,                 2.285228997322329f},
    {-1.1195289977703462f,  0.f,                 1.865881662950577f},
    {-0.4570457994644658f,  0.f,                 2.285228997322329f},
    {-1.445305721320277f,   2.890611442640554f,  1.445305721320277f},
    {-1.7701307697799304f,  2.360174359706574f,  1.7701307697799304f},
};
__constant__ int cLM2L[16] = {0,1,1,1, 2,2,2,2, 2,3,3,3, 3,3,3,3};

#define K2E (-2.8853900817779268f)   // -2*log2(e)

__device__ __forceinline__ float ex2(float a) {
    float r; asm("ex2.approx.f32 %0, %1;" : "=f"(r) : "f"(a)); return r;
}
__device__ __forceinline__ float cutoff(float r) {
    const float u = __saturatef(fmaf(r, 2.0f, -9.0f));
    return fmaf(cospif(u), 0.5f, 0.5f);
}

// ---- K0: reset list heads ----
__global__ void __launch_bounds__(256) init_heads_kernel(int nseg) {
    int s = blockIdx.x * blockDim.x + threadIdx.x;
    if (s < nseg) g_head[s] = -1;
}

// ---- K1: bucket edges into per-segment linked lists ----
__global__ void __launch_bounds__(256) build_lists_kernel(
    const int* __restrict__ zspec,
    const int* __restrict__ idx_i,
    const int* __restrict__ idx_j,
    int J)
{
    int e = blockIdx.x * blockDim.x + threadIdx.x;
    if (e >= J) return;
    const int seg = (__ldg(idx_i + e) << 2) + __ldg(zspec + __ldg(idx_j + e));
    g_next[e] = atomicExch(&g_head[seg], e);
}

// ---- K2: one warp per segment, register accumulation, no atomics ----
__global__ void __launch_bounds__(256) gather_kernel(
    const float* __restrict__ dist,
    const float* __restrict__ dirs,      // [J,3]
    const float* __restrict__ centers,   // [32]
    float*       __restrict__ out,       // [nseg * 128]
    int nseg)
{
    const int lane  = threadIdx.x & 31;
    const int warp  = (blockIdx.x * blockDim.x + threadIdx.x) >> 5;
    const int nwarp = (gridDim.x * blockDim.x) >> 5;

    const int lm = lane & 15;
    const int h  = lane >> 4;            // parity of owned n
    const int l  = cLM2L[lm];

    // per-lane constants
    const float cen = centers[lane];     // lane = 8*l' + n' -> rb[k=lane]
    const float C0 = cC[lm][0], C1 = cC[lm][1], C2 = cC[lm][2];
    const int fs = cFS[lm];
    const int pi = cPQ[lm][0], qi = cPQ[lm][1];
    const bool f_y = (fs == 2), f_z = (fs == 3), f_one = (fs == 0);
    const bool p_y = (pi == 1), p_z = (pi == 2);
    const bool q_y = (qi == 1), q_z = (qi == 2);

    // rb shuffle sources: rb[l][n] computed by lane 8*l+n; owned n = h+2k
    const int sR0 = 8*l + h;
    const int sR1 = sR0 + 2;
    const int sR2 = sR0 + 4;
    const int sR3 = sR0 + 6;

    const unsigned msk = 0xffffffffu;

    for (int s = warp; s < nseg; s += nwarp) {
        float a0 = 0.f, a1 = 0.f, a2 = 0.f, a3 = 0.f;

        int e = g_head[s];               // warp-uniform broadcast load
        while (e >= 0) {
            // issue chain load FIRST, data loads in its shadow
            const int   en = g_next[e];
            const float r  = __ldg(dist + e);
            const float x  = __ldg(dirs + 3*e + 0);
            const float y  = __ldg(dirs + 3*e + 1);
            const float z  = __ldg(dirs + 3*e + 2);

            // rb for this lane's center, cutoff folded in (pre-shuffle)
            const float t  = r - cen;
            const float rb = ex2(K2E * t * t) * cutoff(r);

            // Y = f1 * (C0 + C1*P*Q + C2*z^2) for this lane's lm
            const float Pv = p_y ? y : (p_z ? z : x);
            const float Qv = q_y ? y : (q_z ? z : x);
            const float f2 = fmaf(C1, Pv * Qv, fmaf(C2, z * z, C0));
            const float F1 = f_y ? y : (f_z ? z : x);
            const float Y  = f_one ? f2 : F1 * f2;

            // gather the 4 rb values (n = h, h+2, h+4, h+6)
            const float R0 = __shfl_sync(msk, rb, sR0);
            const float R1 = __shfl_sync(msk, rb, sR1);
            const float R2 = __shfl_sync(msk, rb, sR2);
            const float R3 = __shfl_sync(msk, rb, sR3);

            a0 = fmaf(Y, R0, a0);
            a1 = fmaf(Y, R1, a1);
            a2 = fmaf(Y, R2, a2);
            a3 = fmaf(Y, R3, a3);

            e = en;
        }

        // coalesced stores: 4 x 128B wavefronts; empty segments write zeros
        float* p = out + ((size_t)s << 7) + lane;
        p[0]  = a0;
        p[32] = a1;
        p[64] = a2;
        p[96] = a3;
    }
}

extern "C" void kernel_launch(void* const* d_in, const int* in_sizes, int n_in,
                              void* d_out, int out_size) {
    const float* dist    = (const float*)d_in[0];
    const float* dirs    = (const float*)d_in[1];
    const float* centers = (const float*)d_in[2];
    const int*   zspec   = (const int*)d_in[3];
    const int*   idx_i   = (const int*)d_in[4];
    const int*   idx_j   = (const int*)d_in[5];
    float*       out     = (float*)d_out;
    const int J    = in_sizes[0];
    const int nseg = out_size >> 7;      // 128 floats per segment

    // K0: reset heads
    init_heads_kernel<<<(nseg + 255) / 256, 256>>>(nseg);

    // K1: bucket edges (one 4B atomicExch per edge)
    build_lists_kernel<<<(J + 255) / 256, 256>>>(zspec, idx_i, idx_j, J);

    // K2: gather — one resident wave at actual occupancy
    int nsm = 148, occ = 6;
    cudaDeviceGetAttribute(&nsm, cudaDevAttrMultiProcessorCount, 0);
    cudaOccupancyMaxActiveBlocksPerMultiprocessor(&occ, gather_kernel, 256, 0);
    if (occ < 1) occ = 1;
    gather_kernel<<<nsm * occ, 256>>>(dist, dirs, centers, out, nseg);
}